// round 12
// baseline (speedup 1.0000x reference)
#include <cuda_runtime.h>
#include <cuda_bf16.h>
#include <cstddef>

#define N_NODES 100000
#define N_EDGES 1200000
#define HID 64
#define F_IN 16
#define G_GRAPHS 1024
#define CAP 96            // max in-degree capacity (Poisson(12): overflow ~1e-26)

// ---------------- scratch (device globals; no allocation) ----------------
__device__ float g_c1  [(size_t)N_NODES * F_IN];
__device__ float g_h1  [(size_t)N_NODES * HID];
__device__ float g_h2  [(size_t)N_NODES * HID];
__device__ int   g_deg [N_NODES];
__device__ int   g_bucket[(size_t)N_NODES * CAP];
__device__ float g_stats[3][2 * HID];

// BN scale/shift from accumulated sum/sumsq (training-mode batch stats)
__device__ __forceinline__ void bn_coeffs(const float* __restrict__ stats,
                                          const float* __restrict__ gamma,
                                          const float* __restrict__ beta,
                                          float* sc, float* sh) {
    int t = threadIdx.x;
    if (t < HID) {
        const float invN = 1.0f / (float)N_NODES;
        float mean = stats[t] * invN;
        float var  = stats[HID + t] * invN - mean * mean;
        float s    = gamma[t] * rsqrtf(var + 1e-5f);
        sc[t] = s;
        sh[t] = beta[t] - mean * s;
    }
}

// ---------------- zero pass ----------------
__global__ void zero_misc_kernel() {
    int i = blockIdx.x * blockDim.x + threadIdx.x;
    if (i < N_NODES)     g_deg[i] = 0;
    if (i < 3 * 2 * HID) ((float*)g_stats)[i] = 0.0f;
}

// ---------------- bucket build (once, reused by all 3 layers) ----------------
__global__ __launch_bounds__(256)
void bucket_kernel(const int* __restrict__ src, const int* __restrict__ dst) {
    int e = blockIdx.x * blockDim.x + threadIdx.x;
    if (e >= N_EDGES) return;
    int d = dst[e];
    int pos = atomicAdd(&g_deg[d], 1);
    if (pos < CAP) g_bucket[(size_t)d * CAP + pos] = src[e];
}

// ---------------- layer-1 gather-aggregate (16-wide, no BN) ----------------
__global__ __launch_bounds__(256)
void aggr16_kernel(const float* __restrict__ x,
                   const float* __restrict__ eps_p,
                   float* __restrict__ out) {
    int idx = blockIdx.x * blockDim.x + threadIdx.x;
    if (idx >= N_NODES * 4) return;
    int n = idx >> 2, q = idx & 3;
    int deg = min(g_deg[n], CAP);
    float epsv = 1.0f + *eps_p;
    float4 v = reinterpret_cast<const float4*>(x + (size_t)n * F_IN)[q];
    float4 a0 = make_float4(epsv * v.x, epsv * v.y, epsv * v.z, epsv * v.w);
    float4 a1 = make_float4(0, 0, 0, 0);
    const int* bk = g_bucket + (size_t)n * CAP;
    int i = 0;
    for (; i + 2 <= deg; i += 2) {
        int s0 = bk[i], s1 = bk[i + 1];
        float4 m0 = reinterpret_cast<const float4*>(x + (size_t)s0 * F_IN)[q];
        float4 m1 = reinterpret_cast<const float4*>(x + (size_t)s1 * F_IN)[q];
        a0.x += m0.x; a0.y += m0.y; a0.z += m0.z; a0.w += m0.w;
        a1.x += m1.x; a1.y += m1.y; a1.z += m1.z; a1.w += m1.w;
    }
    if (i < deg) {
        int s0 = bk[i];
        float4 m0 = reinterpret_cast<const float4*>(x + (size_t)s0 * F_IN)[q];
        a0.x += m0.x; a0.y += m0.y; a0.z += m0.z; a0.w += m0.w;
    }
    a0.x += a1.x; a0.y += a1.y; a0.z += a1.z; a0.w += a1.w;
    reinterpret_cast<float4*>(out + (size_t)n * F_IN)[q] = a0;
}

// ---------------- 64-wide gather-aggregate, BN after sum, batched loads -----
// out[n] = sc * ((1+eps)*h_n + sum_j h_j) + (deg + 1 + eps) * sh
// Inner loop preloads 8 neighbor rows back-to-back (8 LDGs in flight) before
// consuming; invalid slots read node 0's row (hot) and are skipped by a
// warp-uniform predicate.
__global__ __launch_bounds__(256)
void aggr64_kernel(const float* __restrict__ h,
                   const float* __restrict__ stats,
                   const float* __restrict__ gamma,
                   const float* __restrict__ beta,
                   const float* __restrict__ eps_p,
                   float* __restrict__ out) {
    __shared__ float sc[HID], sh[HID];
    bn_coeffs(stats, gamma, beta, sc, sh);
    __syncthreads();

    int gw = (blockIdx.x * blockDim.x + threadIdx.x) >> 5;
    if (gw >= N_NODES) return;
    int lane = threadIdx.x & 31;
    float2 scl = *reinterpret_cast<const float2*>(&sc[2 * lane]);
    float2 shf = *reinterpret_cast<const float2*>(&sh[2 * lane]);

    int deg = min(g_deg[gw], CAP);
    float epsv = 1.0f + *eps_p;

    float2 v = reinterpret_cast<const float2*>(h + (size_t)gw * HID)[lane];
    float2 a0 = {0, 0}, a1 = {0, 0};

    const int* bk = g_bucket + (size_t)gw * CAP;
    for (int base = 0; base < deg; base += 32) {
        int cnt = min(32, deg - base);                 // warp-uniform
        int s = (lane < cnt) ? bk[base + lane] : 0;
        for (int b = 0; b < cnt; b += 8) {             // warp-uniform trips
            float2 m[8];
#pragma unroll
            for (int i = 0; i < 8; i++) {
                int si = __shfl_sync(0xffffffffu, s, b + i);
                m[i] = reinterpret_cast<const float2*>(h + (size_t)si * HID)[lane];
            }
            int c8 = cnt - b;                          // warp-uniform
#pragma unroll
            for (int i = 0; i < 8; i++) {
                if (i < c8) {
                    if (i & 1) { a1.x += m[i].x; a1.y += m[i].y; }
                    else       { a0.x += m[i].x; a0.y += m[i].y; }
                }
            }
        }
    }
    float2 S;
    S.x = a0.x + a1.x;
    S.y = a0.y + a1.y;
    float cnt_sh = (float)deg + epsv;
    float2 o;
    o.x = fmaf(scl.x, fmaf(epsv, v.x, S.x), cnt_sh * shf.x);
    o.y = fmaf(scl.y, fmaf(epsv, v.y, S.y), cnt_sh * shf.y);
    reinterpret_cast<float2*>(out + (size_t)gw * HID)[lane] = o;
}

// ---------------- GEMM [N,K]@[K,64] + bias + ReLU (scalar tile) -------------
// 256 threads; tile ROWS x 64; thread: (ROWS/16) rows x 4 cols; k-vec by 4.
template <int K, int ROWS, int MINB, bool STATS>
__global__ __launch_bounds__(256, MINB)
void gemm_kernel(const float* __restrict__ X,
                 const float* __restrict__ W,
                 const float* __restrict__ bias,
                 float* __restrict__ out,
                 float* __restrict__ stats_out) {
    constexpr int RJ = ROWS / 16;
    __shared__ float sW[K * 64];
    __shared__ float sIn[ROWS * K];
    __shared__ float sSum[HID], sSq[HID];

    const int tid = threadIdx.x;
    const int tx  = tid & 15;
    const int ty  = tid >> 4;
    const size_t row0 = (size_t)blockIdx.x * ROWS;

    if (STATS && tid < HID) { sSum[tid] = 0.0f; sSq[tid] = 0.0f; }

    for (int i = tid; i < K * 64; i += 256) sW[i] = W[i];

    for (int i = tid; i < ROWS * K; i += 256) {
        size_t r = row0 + (size_t)(i / K);
        sIn[i] = (r < N_NODES) ? X[row0 * K + i] : 0.0f;
    }
    __syncthreads();

    float4 acc[RJ];
#pragma unroll
    for (int j = 0; j < RJ; j++) acc[j] = make_float4(0, 0, 0, 0);

#pragma unroll
    for (int k = 0; k < K; k += 4) {
        float4 w0 = *reinterpret_cast<const float4*>(&sW[(k + 0) * 64 + tx * 4]);
        float4 w1 = *reinterpret_cast<const float4*>(&sW[(k + 1) * 64 + tx * 4]);
        float4 w2 = *reinterpret_cast<const float4*>(&sW[(k + 2) * 64 + tx * 4]);
        float4 w3 = *reinterpret_cast<const float4*>(&sW[(k + 3) * 64 + tx * 4]);
#pragma unroll
        for (int j = 0; j < RJ; j++) {
            float4 a = *reinterpret_cast<const float4*>(&sIn[(ty * RJ + j) * K + k]);
            acc[j].x = fmaf(a.x, w0.x, acc[j].x);
            acc[j].y = fmaf(a.x, w0.y, acc[j].y);
            acc[j].z = fmaf(a.x, w0.z, acc[j].z);
            acc[j].w = fmaf(a.x, w0.w, acc[j].w);
            acc[j].x = fmaf(a.y, w1.x, acc[j].x);
            acc[j].y = fmaf(a.y, w1.y, acc[j].y);
            acc[j].z = fmaf(a.y, w1.z, acc[j].z);
            acc[j].w = fmaf(a.y, w1.w, acc[j].w);
            acc[j].x = fmaf(a.z, w2.x, acc[j].x);
            acc[j].y = fmaf(a.z, w2.y, acc[j].y);
            acc[j].z = fmaf(a.z, w2.z, acc[j].z);
            acc[j].w = fmaf(a.z, w2.w, acc[j].w);
            acc[j].x = fmaf(a.w, w3.x, acc[j].x);
            acc[j].y = fmaf(a.w, w3.y, acc[j].y);
            acc[j].z = fmaf(a.w, w3.z, acc[j].z);
            acc[j].w = fmaf(a.w, w3.w, acc[j].w);
        }
    }

    const float4 bv = reinterpret_cast<const float4*>(bias)[tx];
    float4 ls = make_float4(0, 0, 0, 0), lss = make_float4(0, 0, 0, 0);
#pragma unroll
    for (int j = 0; j < RJ; j++) {
        size_t row = row0 + ty * RJ + j;
        if (row >= N_NODES) break;
        float4 o;
        o.x = fmaxf(acc[j].x + bv.x, 0.0f);
        o.y = fmaxf(acc[j].y + bv.y, 0.0f);
        o.z = fmaxf(acc[j].z + bv.z, 0.0f);
        o.w = fmaxf(acc[j].w + bv.w, 0.0f);
        reinterpret_cast<float4*>(out + row * 64)[tx] = o;
        if (STATS) {
            ls.x += o.x; ls.y += o.y; ls.z += o.z; ls.w += o.w;
            lss.x += o.x * o.x; lss.y += o.y * o.y;
            lss.z += o.z * o.z; lss.w += o.w * o.w;
        }
    }

    if (STATS) {
        atomicAdd(&sSum[tx * 4 + 0], ls.x);
        atomicAdd(&sSum[tx * 4 + 1], ls.y);
        atomicAdd(&sSum[tx * 4 + 2], ls.z);
        atomicAdd(&sSum[tx * 4 + 3], ls.w);
        atomicAdd(&sSq[tx * 4 + 0], lss.x);
        atomicAdd(&sSq[tx * 4 + 1], lss.y);
        atomicAdd(&sSq[tx * 4 + 2], lss.z);
        atomicAdd(&sSq[tx * 4 + 3], lss.w);
        __syncthreads();
        if (tid < HID) {
            atomicAdd(&stats_out[tid],       sSum[tid]);
            atomicAdd(&stats_out[HID + tid], sSq[tid]);
        }
    }
}

// ---------------- fused BN3 + mean-pool + readout (batch is sorted) ---------
__global__ __launch_bounds__(128)
void pool_readout_kernel(const float* __restrict__ h,
                         const int* __restrict__ batch,
                         const float* __restrict__ stats,
                         const float* __restrict__ gamma,
                         const float* __restrict__ beta,
                         const float* __restrict__ Wf1,
                         const float* __restrict__ bf1,
                         const float* __restrict__ Wf2,
                         const float* __restrict__ bf2,
                         float* __restrict__ out) {
    __shared__ float sc[HID], sh[HID];
    __shared__ float part[4][HID];
    __shared__ float pooled[HID];
    __shared__ float hid[10];

    const int g   = blockIdx.x;
    const int tid = threadIdx.x;

    if (tid < HID) {
        const float invN = 1.0f / (float)N_NODES;
        float mean = stats[tid] * invN;
        float var  = stats[HID + tid] * invN - mean * mean;
        float s    = gamma[tid] * rsqrtf(var + 1e-5f);
        sc[tid] = s;
        sh[tid] = beta[tid] - mean * s;
    }

    int lo = 0, hi = N_NODES;
    while (lo < hi) { int m = (lo + hi) >> 1; if (batch[m] < g)     lo = m + 1; else hi = m; }
    const int start = lo;
    lo = start; hi = N_NODES;
    while (lo < hi) { int m = (lo + hi) >> 1; if (batch[m] < g + 1) lo = m + 1; else hi = m; }
    const int end = lo;

    const int cp = tid & 31;
    const int rg = tid >> 5;
    float2 a = make_float2(0, 0);
    for (int r = start + rg; r < end; r += 4) {
        float2 v = reinterpret_cast<const float2*>(h + (size_t)r * HID)[cp];
        a.x += v.x; a.y += v.y;
    }
    part[rg][cp * 2]     = a.x;
    part[rg][cp * 2 + 1] = a.y;
    __syncthreads();

    if (tid < 32) {
        float inv = 1.0f / fmaxf((float)(end - start), 1.0f);
        int c = tid * 2;
        float sx = part[0][c] + part[1][c] + part[2][c] + part[3][c];
        float sy = part[0][c + 1] + part[1][c + 1] + part[2][c + 1] + part[3][c + 1];
        pooled[c]     = (sx * inv) * sc[c]     + sh[c];
        pooled[c + 1] = (sy * inv) * sc[c + 1] + sh[c + 1];
    }
    __syncthreads();

    if (tid < 10) {
        float acc = bf1[tid];
        for (int k = 0; k < 64; k++) acc += pooled[k] * Wf1[k * 10 + tid];
        hid[tid] = fmaxf(acc, 0.0f);
    }
    __syncthreads();

    if (tid == 0) {
        float o = bf2[0];
#pragma unroll
        for (int j = 0; j < 10; j++) o += hid[j] * Wf2[j];
        out[g] = o;
    }
}

// ---------------- host launcher ----------------
static inline int cdiv(long long a, int b) { return (int)((a + b - 1) / b); }

extern "C" void kernel_launch(void* const* d_in, const int* in_sizes, int n_in,
                              void* d_out, int out_size) {
    (void)in_sizes; (void)n_in; (void)out_size;
    const float* x     = (const float*)d_in[0];
    const int*   ei    = (const int*)  d_in[1];
    const int*   batch = (const int*)  d_in[2];
    const float* W1a = (const float*)d_in[3];  const float* b1a = (const float*)d_in[4];
    const float* W1b = (const float*)d_in[5];  const float* b1b = (const float*)d_in[6];
    const float* e1  = (const float*)d_in[7];
    const float* g1  = (const float*)d_in[8];  const float* be1 = (const float*)d_in[9];
    const float* W2a = (const float*)d_in[10]; const float* b2a = (const float*)d_in[11];
    const float* W2b = (const float*)d_in[12]; const float* b2b = (const float*)d_in[13];
    const float* e2  = (const float*)d_in[14];
    const float* g2  = (const float*)d_in[15]; const float* be2 = (const float*)d_in[16];
    const float* W3a = (const float*)d_in[17]; const float* b3a = (const float*)d_in[18];
    const float* W3b = (const float*)d_in[19]; const float* b3b = (const float*)d_in[20];
    const float* e3  = (const float*)d_in[21];
    const float* g3  = (const float*)d_in[22]; const float* be3 = (const float*)d_in[23];
    const float* Wf1 = (const float*)d_in[24]; const float* bf1 = (const float*)d_in[25];
    const float* Wf2 = (const float*)d_in[26]; const float* bf2 = (const float*)d_in[27];
    float* out = (float*)d_out;

    const int* src = ei;
    const int* dst = ei + N_EDGES;

    void *p_c1, *p_h1, *p_h2, *p_stats;
    cudaGetSymbolAddress(&p_c1, g_c1);
    cudaGetSymbolAddress(&p_h1, g_h1);
    cudaGetSymbolAddress(&p_h2, g_h2);
    cudaGetSymbolAddress(&p_stats, g_stats);
    float* c1 = (float*)p_c1;
    float* h1 = (float*)p_h1;
    float* h2 = (float*)p_h2;
    float* st0 = (float*)p_stats;
    float* st1 = st0 + 2 * HID;
    float* st2 = st0 + 4 * HID;

    const int TB = 256;
    const int GB64R = cdiv(N_NODES, 64);   // 1563 (all GEMMs: 64-row tiles)

    zero_misc_kernel<<<cdiv(N_NODES, TB), TB>>>();
    bucket_kernel<<<cdiv(N_EDGES, TB), TB>>>(src, dst);

    // ===== layer 1 =====
    aggr16_kernel<<<cdiv(N_NODES * 4, TB), TB>>>(x, e1, c1);
    gemm_kernel<F_IN, 64, 4, false><<<GB64R, TB>>>(c1, W1a, b1a, h1, nullptr);
    gemm_kernel<HID,  64, 4, true ><<<GB64R, TB>>>(h1, W1b, b1b, h2, st0);

    // ===== layer 2 =====
    aggr64_kernel<<<cdiv(N_NODES * 32, TB), TB>>>(h2, st0, g1, be1, e2, h1);
    gemm_kernel<HID, 64, 4, false><<<GB64R, TB>>>(h1, W2a, b2a, h2, nullptr);
    gemm_kernel<HID, 64, 4, true ><<<GB64R, TB>>>(h2, W2b, b2b, h1, st1);

    // ===== layer 3 =====
    aggr64_kernel<<<cdiv(N_NODES * 32, TB), TB>>>(h1, st1, g2, be2, e3, h2);
    gemm_kernel<HID, 64, 4, false><<<GB64R, TB>>>(h2, W3a, b3a, h1, nullptr);
    gemm_kernel<HID, 64, 4, true ><<<GB64R, TB>>>(h1, W3b, b3b, h2, st2);

    // ===== fused BN3 + mean-pool + readout =====
    pool_readout_kernel<<<G_GRAPHS, 128>>>(h2, batch, st2, g3, be3,
                                           Wf1, bf1, Wf2, bf2, out);
}

// round 13
// speedup vs baseline: 1.0500x; 1.0500x over previous
#include <cuda_runtime.h>
#include <cuda_bf16.h>
#include <cstddef>

#define N_NODES 100000
#define N_EDGES 1200000
#define HID 64
#define F_IN 16
#define G_GRAPHS 1024
#define CAP 96            // max in-degree capacity (Poisson(12): overflow ~1e-26)

// ---------------- scratch (device globals; no allocation) ----------------
__device__ float g_c1  [(size_t)N_NODES * F_IN];
__device__ float g_h1  [(size_t)N_NODES * HID];
__device__ float g_h2  [(size_t)N_NODES * HID];
__device__ int   g_deg [N_NODES];
__device__ int   g_bucket[(size_t)N_NODES * CAP];
__device__ float g_stats[3][2 * HID];

// BN scale/shift from accumulated sum/sumsq (training-mode batch stats)
__device__ __forceinline__ void bn_coeffs(const float* __restrict__ stats,
                                          const float* __restrict__ gamma,
                                          const float* __restrict__ beta,
                                          float* sc, float* sh) {
    int t = threadIdx.x;
    if (t < HID) {
        const float invN = 1.0f / (float)N_NODES;
        float mean = stats[t] * invN;
        float var  = stats[HID + t] * invN - mean * mean;
        float s    = gamma[t] * rsqrtf(var + 1e-5f);
        sc[t] = s;
        sh[t] = beta[t] - mean * s;
    }
}

// ---------------- zero pass ----------------
__global__ void zero_misc_kernel() {
    int i = blockIdx.x * blockDim.x + threadIdx.x;
    if (i < N_NODES)     g_deg[i] = 0;
    if (i < 3 * 2 * HID) ((float*)g_stats)[i] = 0.0f;
}

// ---------------- bucket build (once, reused by all 3 layers) ----------------
__global__ __launch_bounds__(256)
void bucket_kernel(const int* __restrict__ src, const int* __restrict__ dst) {
    int e = blockIdx.x * blockDim.x + threadIdx.x;
    if (e >= N_EDGES) return;
    int d = dst[e];
    int pos = atomicAdd(&g_deg[d], 1);
    if (pos < CAP) g_bucket[(size_t)d * CAP + pos] = src[e];
}

// ---------------- layer-1 gather-aggregate (16-wide, no BN) ----------------
__global__ __launch_bounds__(256)
void aggr16_kernel(const float* __restrict__ x,
                   const float* __restrict__ eps_p,
                   float* __restrict__ out) {
    int idx = blockIdx.x * blockDim.x + threadIdx.x;
    if (idx >= N_NODES * 4) return;
    int n = idx >> 2, q = idx & 3;
    int deg = min(g_deg[n], CAP);
    float epsv = 1.0f + *eps_p;
    float4 v = reinterpret_cast<const float4*>(x + (size_t)n * F_IN)[q];
    float4 a0 = make_float4(epsv * v.x, epsv * v.y, epsv * v.z, epsv * v.w);
    float4 a1 = make_float4(0, 0, 0, 0);
    const int* bk = g_bucket + (size_t)n * CAP;
    int i = 0;
    for (; i + 2 <= deg; i += 2) {
        int s0 = bk[i], s1 = bk[i + 1];
        float4 m0 = reinterpret_cast<const float4*>(x + (size_t)s0 * F_IN)[q];
        float4 m1 = reinterpret_cast<const float4*>(x + (size_t)s1 * F_IN)[q];
        a0.x += m0.x; a0.y += m0.y; a0.z += m0.z; a0.w += m0.w;
        a1.x += m1.x; a1.y += m1.y; a1.z += m1.z; a1.w += m1.w;
    }
    if (i < deg) {
        int s0 = bk[i];
        float4 m0 = reinterpret_cast<const float4*>(x + (size_t)s0 * F_IN)[q];
        a0.x += m0.x; a0.y += m0.y; a0.z += m0.z; a0.w += m0.w;
    }
    a0.x += a1.x; a0.y += a1.y; a0.z += a1.z; a0.w += a1.w;
    reinterpret_cast<float4*>(out + (size_t)n * F_IN)[q] = a0;
}

// ---------------- 64-wide gather-aggregate: half-warp per node --------------
// Each 16-lane half-warp owns one node; lane owns 4 cols (float4/LDG.128).
// Two independent gather chains per warp -> 2x memory-level parallelism.
// BN applied after the sum: out = sc*((1+eps)*h_n + S) + (deg+1+eps)*sh.
__global__ __launch_bounds__(256)
void aggr64_kernel(const float* __restrict__ h,
                   const float* __restrict__ stats,
                   const float* __restrict__ gamma,
                   const float* __restrict__ beta,
                   const float* __restrict__ eps_p,
                   float* __restrict__ out) {
    __shared__ float sc[HID], sh[HID];
    bn_coeffs(stats, gamma, beta, sc, sh);
    __syncthreads();

    int gidx = blockIdx.x * blockDim.x + threadIdx.x;
    int n = gidx >> 4;                    // half-warp per node
    if (n >= N_NODES) return;
    int hl = threadIdx.x & 15;            // lane within half (0..15)

    float4 scl = *reinterpret_cast<const float4*>(&sc[4 * hl]);
    float4 shf = *reinterpret_cast<const float4*>(&sh[4 * hl]);

    int deg = min(g_deg[n], CAP);
    float epsv = 1.0f + *eps_p;

    float4 v = reinterpret_cast<const float4*>(h + (size_t)n * HID)[hl];
    float4 a0 = {0, 0, 0, 0}, a1 = {0, 0, 0, 0};
    float4 a2 = {0, 0, 0, 0}, a3 = {0, 0, 0, 0};

    const int* bk = g_bucket + (size_t)n * CAP;
    for (int base = 0; base < deg; base += 16) {
        int cnt = min(16, deg - base);    // uniform within the half
        int s = (hl < cnt) ? bk[base + hl] : 0;
        int i = 0;
        for (; i + 4 <= cnt; i += 4) {
            int s0 = __shfl_sync(0xffffffffu, s, i,     16);
            int s1 = __shfl_sync(0xffffffffu, s, i + 1, 16);
            int s2 = __shfl_sync(0xffffffffu, s, i + 2, 16);
            int s3 = __shfl_sync(0xffffffffu, s, i + 3, 16);
            float4 m0 = reinterpret_cast<const float4*>(h + (size_t)s0 * HID)[hl];
            float4 m1 = reinterpret_cast<const float4*>(h + (size_t)s1 * HID)[hl];
            float4 m2 = reinterpret_cast<const float4*>(h + (size_t)s2 * HID)[hl];
            float4 m3 = reinterpret_cast<const float4*>(h + (size_t)s3 * HID)[hl];
            a0.x += m0.x; a0.y += m0.y; a0.z += m0.z; a0.w += m0.w;
            a1.x += m1.x; a1.y += m1.y; a1.z += m1.z; a1.w += m1.w;
            a2.x += m2.x; a2.y += m2.y; a2.z += m2.z; a2.w += m2.w;
            a3.x += m3.x; a3.y += m3.y; a3.z += m3.z; a3.w += m3.w;
        }
        for (; i < cnt; i++) {
            int s0 = __shfl_sync(0xffffffffu, s, i, 16);
            float4 m0 = reinterpret_cast<const float4*>(h + (size_t)s0 * HID)[hl];
            a0.x += m0.x; a0.y += m0.y; a0.z += m0.z; a0.w += m0.w;
        }
    }
    float4 S;
    S.x = (a0.x + a1.x) + (a2.x + a3.x);
    S.y = (a0.y + a1.y) + (a2.y + a3.y);
    S.z = (a0.z + a1.z) + (a2.z + a3.z);
    S.w = (a0.w + a1.w) + (a2.w + a3.w);
    float cnt_sh = (float)deg + epsv;
    float4 o;
    o.x = fmaf(scl.x, fmaf(epsv, v.x, S.x), cnt_sh * shf.x);
    o.y = fmaf(scl.y, fmaf(epsv, v.y, S.y), cnt_sh * shf.y);
    o.z = fmaf(scl.z, fmaf(epsv, v.z, S.z), cnt_sh * shf.z);
    o.w = fmaf(scl.w, fmaf(epsv, v.w, S.w), cnt_sh * shf.w);
    reinterpret_cast<float4*>(out + (size_t)n * HID)[hl] = o;
}

// ---------------- GEMM [N,K]@[K,64] + bias + ReLU (scalar tile) -------------
// 256 threads; tile ROWS x 64; thread: (ROWS/16) rows x 4 cols; k-vec by 4.
template <int K, int ROWS, int MINB, bool STATS>
__global__ __launch_bounds__(256, MINB)
void gemm_kernel(const float* __restrict__ X,
                 const float* __restrict__ W,
                 const float* __restrict__ bias,
                 float* __restrict__ out,
                 float* __restrict__ stats_out) {
    constexpr int RJ = ROWS / 16;
    __shared__ float sW[K * 64];
    __shared__ float sIn[ROWS * K];
    __shared__ float sSum[HID], sSq[HID];

    const int tid = threadIdx.x;
    const int tx  = tid & 15;
    const int ty  = tid >> 4;
    const size_t row0 = (size_t)blockIdx.x * ROWS;

    if (STATS && tid < HID) { sSum[tid] = 0.0f; sSq[tid] = 0.0f; }

    for (int i = tid; i < K * 64; i += 256) sW[i] = W[i];

    for (int i = tid; i < ROWS * K; i += 256) {
        size_t r = row0 + (size_t)(i / K);
        sIn[i] = (r < N_NODES) ? X[row0 * K + i] : 0.0f;
    }
    __syncthreads();

    float4 acc[RJ];
#pragma unroll
    for (int j = 0; j < RJ; j++) acc[j] = make_float4(0, 0, 0, 0);

#pragma unroll
    for (int k = 0; k < K; k += 4) {
        float4 w0 = *reinterpret_cast<const float4*>(&sW[(k + 0) * 64 + tx * 4]);
        float4 w1 = *reinterpret_cast<const float4*>(&sW[(k + 1) * 64 + tx * 4]);
        float4 w2 = *reinterpret_cast<const float4*>(&sW[(k + 2) * 64 + tx * 4]);
        float4 w3 = *reinterpret_cast<const float4*>(&sW[(k + 3) * 64 + tx * 4]);
#pragma unroll
        for (int j = 0; j < RJ; j++) {
            float4 a = *reinterpret_cast<const float4*>(&sIn[(ty * RJ + j) * K + k]);
            acc[j].x = fmaf(a.x, w0.x, acc[j].x);
            acc[j].y = fmaf(a.x, w0.y, acc[j].y);
            acc[j].z = fmaf(a.x, w0.z, acc[j].z);
            acc[j].w = fmaf(a.x, w0.w, acc[j].w);
            acc[j].x = fmaf(a.y, w1.x, acc[j].x);
            acc[j].y = fmaf(a.y, w1.y, acc[j].y);
            acc[j].z = fmaf(a.y, w1.z, acc[j].z);
            acc[j].w = fmaf(a.y, w1.w, acc[j].w);
            acc[j].x = fmaf(a.z, w2.x, acc[j].x);
            acc[j].y = fmaf(a.z, w2.y, acc[j].y);
            acc[j].z = fmaf(a.z, w2.z, acc[j].z);
            acc[j].w = fmaf(a.z, w2.w, acc[j].w);
            acc[j].x = fmaf(a.w, w3.x, acc[j].x);
            acc[j].y = fmaf(a.w, w3.y, acc[j].y);
            acc[j].z = fmaf(a.w, w3.z, acc[j].z);
            acc[j].w = fmaf(a.w, w3.w, acc[j].w);
        }
    }

    const float4 bv = reinterpret_cast<const float4*>(bias)[tx];
    float4 ls = make_float4(0, 0, 0, 0), lss = make_float4(0, 0, 0, 0);
#pragma unroll
    for (int j = 0; j < RJ; j++) {
        size_t row = row0 + ty * RJ + j;
        if (row >= N_NODES) break;
        float4 o;
        o.x = fmaxf(acc[j].x + bv.x, 0.0f);
        o.y = fmaxf(acc[j].y + bv.y, 0.0f);
        o.z = fmaxf(acc[j].z + bv.z, 0.0f);
        o.w = fmaxf(acc[j].w + bv.w, 0.0f);
        reinterpret_cast<float4*>(out + row * 64)[tx] = o;
        if (STATS) {
            ls.x += o.x; ls.y += o.y; ls.z += o.z; ls.w += o.w;
            lss.x += o.x * o.x; lss.y += o.y * o.y;
            lss.z += o.z * o.z; lss.w += o.w * o.w;
        }
    }

    if (STATS) {
        atomicAdd(&sSum[tx * 4 + 0], ls.x);
        atomicAdd(&sSum[tx * 4 + 1], ls.y);
        atomicAdd(&sSum[tx * 4 + 2], ls.z);
        atomicAdd(&sSum[tx * 4 + 3], ls.w);
        atomicAdd(&sSq[tx * 4 + 0], lss.x);
        atomicAdd(&sSq[tx * 4 + 1], lss.y);
        atomicAdd(&sSq[tx * 4 + 2], lss.z);
        atomicAdd(&sSq[tx * 4 + 3], lss.w);
        __syncthreads();
        if (tid < HID) {
            atomicAdd(&stats_out[tid],       sSum[tid]);
            atomicAdd(&stats_out[HID + tid], sSq[tid]);
        }
    }
}

// ---------------- fused BN3 + mean-pool + readout (batch is sorted) ---------
__global__ __launch_bounds__(128)
void pool_readout_kernel(const float* __restrict__ h,
                         const int* __restrict__ batch,
                         const float* __restrict__ stats,
                         const float* __restrict__ gamma,
                         const float* __restrict__ beta,
                         const float* __restrict__ Wf1,
                         const float* __restrict__ bf1,
                         const float* __restrict__ Wf2,
                         const float* __restrict__ bf2,
                         float* __restrict__ out) {
    __shared__ float sc[HID], sh[HID];
    __shared__ float part[4][HID];
    __shared__ float pooled[HID];
    __shared__ float hid[10];

    const int g   = blockIdx.x;
    const int tid = threadIdx.x;

    if (tid < HID) {
        const float invN = 1.0f / (float)N_NODES;
        float mean = stats[tid] * invN;
        float var  = stats[HID + tid] * invN - mean * mean;
        float s    = gamma[tid] * rsqrtf(var + 1e-5f);
        sc[tid] = s;
        sh[tid] = beta[tid] - mean * s;
    }

    int lo = 0, hi = N_NODES;
    while (lo < hi) { int m = (lo + hi) >> 1; if (batch[m] < g)     lo = m + 1; else hi = m; }
    const int start = lo;
    lo = start; hi = N_NODES;
    while (lo < hi) { int m = (lo + hi) >> 1; if (batch[m] < g + 1) lo = m + 1; else hi = m; }
    const int end = lo;

    const int cp = tid & 31;
    const int rg = tid >> 5;
    float2 a = make_float2(0, 0);
    for (int r = start + rg; r < end; r += 4) {
        float2 v = reinterpret_cast<const float2*>(h + (size_t)r * HID)[cp];
        a.x += v.x; a.y += v.y;
    }
    part[rg][cp * 2]     = a.x;
    part[rg][cp * 2 + 1] = a.y;
    __syncthreads();

    if (tid < 32) {
        float inv = 1.0f / fmaxf((float)(end - start), 1.0f);
        int c = tid * 2;
        float sx = part[0][c] + part[1][c] + part[2][c] + part[3][c];
        float sy = part[0][c + 1] + part[1][c + 1] + part[2][c + 1] + part[3][c + 1];
        pooled[c]     = (sx * inv) * sc[c]     + sh[c];
        pooled[c + 1] = (sy * inv) * sc[c + 1] + sh[c + 1];
    }
    __syncthreads();

    if (tid < 10) {
        float acc = bf1[tid];
        for (int k = 0; k < 64; k++) acc += pooled[k] * Wf1[k * 10 + tid];
        hid[tid] = fmaxf(acc, 0.0f);
    }
    __syncthreads();

    if (tid == 0) {
        float o = bf2[0];
#pragma unroll
        for (int j = 0; j < 10; j++) o += hid[j] * Wf2[j];
        out[g] = o;
    }
}

// ---------------- host launcher ----------------
static inline int cdiv(long long a, int b) { return (int)((a + b - 1) / b); }

extern "C" void kernel_launch(void* const* d_in, const int* in_sizes, int n_in,
                              void* d_out, int out_size) {
    (void)in_sizes; (void)n_in; (void)out_size;
    const float* x     = (const float*)d_in[0];
    const int*   ei    = (const int*)  d_in[1];
    const int*   batch = (const int*)  d_in[2];
    const float* W1a = (const float*)d_in[3];  const float* b1a = (const float*)d_in[4];
    const float* W1b = (const float*)d_in[5];  const float* b1b = (const float*)d_in[6];
    const float* e1  = (const float*)d_in[7];
    const float* g1  = (const float*)d_in[8];  const float* be1 = (const float*)d_in[9];
    const float* W2a = (const float*)d_in[10]; const float* b2a = (const float*)d_in[11];
    const float* W2b = (const float*)d_in[12]; const float* b2b = (const float*)d_in[13];
    const float* e2  = (const float*)d_in[14];
    const float* g2  = (const float*)d_in[15]; const float* be2 = (const float*)d_in[16];
    const float* W3a = (const float*)d_in[17]; const float* b3a = (const float*)d_in[18];
    const float* W3b = (const float*)d_in[19]; const float* b3b = (const float*)d_in[20];
    const float* e3  = (const float*)d_in[21];
    const float* g3  = (const float*)d_in[22]; const float* be3 = (const float*)d_in[23];
    const float* Wf1 = (const float*)d_in[24]; const float* bf1 = (const float*)d_in[25];
    const float* Wf2 = (const float*)d_in[26]; const float* bf2 = (const float*)d_in[27];
    float* out = (float*)d_out;

    const int* src = ei;
    const int* dst = ei + N_EDGES;

    void *p_c1, *p_h1, *p_h2, *p_stats;
    cudaGetSymbolAddress(&p_c1, g_c1);
    cudaGetSymbolAddress(&p_h1, g_h1);
    cudaGetSymbolAddress(&p_h2, g_h2);
    cudaGetSymbolAddress(&p_stats, g_stats);
    float* c1 = (float*)p_c1;
    float* h1 = (float*)p_h1;
    float* h2 = (float*)p_h2;
    float* st0 = (float*)p_stats;
    float* st1 = st0 + 2 * HID;
    float* st2 = st0 + 4 * HID;

    const int TB = 256;
    const int GB16 = cdiv(N_NODES, 64);    // 1563
    const int GB64 = cdiv(N_NODES, 128);   // 782

    zero_misc_kernel<<<cdiv(N_NODES, TB), TB>>>();
    bucket_kernel<<<cdiv(N_EDGES, TB), TB>>>(src, dst);

    // ===== layer 1 =====
    aggr16_kernel<<<cdiv(N_NODES * 4, TB), TB>>>(x, e1, c1);
    gemm_kernel<F_IN, 64, 4, false><<<GB16, TB>>>(c1, W1a, b1a, h1, nullptr);
    gemm_kernel<HID, 128, 3, true ><<<GB64, TB>>>(h1, W1b, b1b, h2, st0);

    // ===== layer 2 =====
    aggr64_kernel<<<cdiv(N_NODES * 16, TB), TB>>>(h2, st0, g1, be1, e2, h1);
    gemm_kernel<HID, 128, 3, false><<<GB64, TB>>>(h1, W2a, b2a, h2, nullptr);
    gemm_kernel<HID, 128, 3, true ><<<GB64, TB>>>(h2, W2b, b2b, h1, st1);

    // ===== layer 3 =====
    aggr64_kernel<<<cdiv(N_NODES * 16, TB), TB>>>(h1, st1, g2, be2, e3, h2);
    gemm_kernel<HID, 128, 3, false><<<GB64, TB>>>(h2, W3a, b3a, h1, nullptr);
    gemm_kernel<HID, 128, 3, true ><<<GB64, TB>>>(h1, W3b, b3b, h2, st2);

    // ===== fused BN3 + mean-pool + readout =====
    pool_readout_kernel<<<G_GRAPHS, 128>>>(h2, batch, st2, g3, be3,
                                           Wf1, bf1, Wf2, bf2, out);
}

// round 15
// speedup vs baseline: 1.1940x; 1.1371x over previous
#include <cuda_runtime.h>
#include <cuda_bf16.h>
#include <cstddef>

#define N_NODES 100000
#define N_EDGES 1200000
#define HID 64
#define F_IN 16
#define G_GRAPHS 1024
#define CAP 96            // max in-degree capacity (Poisson(12): overflow ~1e-26)

// ---------------- scratch (device globals; no allocation) ----------------
// Invariants across launches: g_deg is zero at launch entry (zero-initialized
// at load; re-zeroed by pool_readout_kernel at the end of every launch).
// g_stats (ALL 384 floats) is zeroed at the start of every launch by
// bucket_kernel block 0.
__device__ float g_c1  [(size_t)N_NODES * F_IN];
__device__ float g_h1  [(size_t)N_NODES * HID];
__device__ float g_h2  [(size_t)N_NODES * HID];
__device__ int   g_deg [N_NODES];
__device__ int   g_bucket[(size_t)N_NODES * CAP];
__device__ float g_stats[3][2 * HID];

// BN scale/shift from accumulated sum/sumsq (training-mode batch stats)
__device__ __forceinline__ void bn_coeffs(const float* __restrict__ stats,
                                          const float* __restrict__ gamma,
                                          const float* __restrict__ beta,
                                          float* sc, float* sh) {
    int t = threadIdx.x;
    if (t < HID) {
        const float invN = 1.0f / (float)N_NODES;
        float mean = stats[t] * invN;
        float var  = stats[HID + t] * invN - mean * mean;
        float s    = gamma[t] * rsqrtf(var + 1e-5f);
        sc[t] = s;
        sh[t] = beta[t] - mean * s;
    }
}

// ---------------- bucket build (also zeroes ALL of g_stats for this launch) -
__global__ __launch_bounds__(256)
void bucket_kernel(const int* __restrict__ src, const int* __restrict__ dst) {
    int e = blockIdx.x * blockDim.x + threadIdx.x;
    if (blockIdx.x == 0) {
        int t = threadIdx.x;
        ((float*)g_stats)[t] = 0.0f;                       // [0,256)
        if (t < 3 * 2 * HID - 256) ((float*)g_stats)[256 + t] = 0.0f;  // [256,384)
    }
    if (e >= N_EDGES) return;
    int d = dst[e];
    int pos = atomicAdd(&g_deg[d], 1);
    if (pos < CAP) g_bucket[(size_t)d * CAP + pos] = src[e];
}

// ---------------- layer-1 gather-aggregate (16-wide, no BN) ----------------
__global__ __launch_bounds__(256)
void aggr16_kernel(const float* __restrict__ x,
                   const float* __restrict__ eps_p,
                   float* __restrict__ out) {
    int idx = blockIdx.x * blockDim.x + threadIdx.x;
    if (idx >= N_NODES * 4) return;
    int n = idx >> 2, q = idx & 3;
    int deg = min(g_deg[n], CAP);
    float epsv = 1.0f + *eps_p;
    float4 v = reinterpret_cast<const float4*>(x + (size_t)n * F_IN)[q];
    float4 a0 = make_float4(epsv * v.x, epsv * v.y, epsv * v.z, epsv * v.w);
    float4 a1 = make_float4(0, 0, 0, 0);
    const int* bk = g_bucket + (size_t)n * CAP;
    int i = 0;
    for (; i + 2 <= deg; i += 2) {
        int s0 = bk[i], s1 = bk[i + 1];
        float4 m0 = reinterpret_cast<const float4*>(x + (size_t)s0 * F_IN)[q];
        float4 m1 = reinterpret_cast<const float4*>(x + (size_t)s1 * F_IN)[q];
        a0.x += m0.x; a0.y += m0.y; a0.z += m0.z; a0.w += m0.w;
        a1.x += m1.x; a1.y += m1.y; a1.z += m1.z; a1.w += m1.w;
    }
    if (i < deg) {
        int s0 = bk[i];
        float4 m0 = reinterpret_cast<const float4*>(x + (size_t)s0 * F_IN)[q];
        a0.x += m0.x; a0.y += m0.y; a0.z += m0.z; a0.w += m0.w;
    }
    a0.x += a1.x; a0.y += a1.y; a0.z += a1.z; a0.w += a1.w;
    reinterpret_cast<float4*>(out + (size_t)n * F_IN)[q] = a0;
}

// ---------------- 64-wide gather-aggregate, BN after sum, 8 loads in flight -
// out[n] = sc * ((1+eps)*h_n + sum_j h_j) + (deg + 1 + eps) * sh
__global__ __launch_bounds__(256)
void aggr64_kernel(const float* __restrict__ h,
                   const float* __restrict__ stats,
                   const float* __restrict__ gamma,
                   const float* __restrict__ beta,
                   const float* __restrict__ eps_p,
                   float* __restrict__ out) {
    __shared__ float sc[HID], sh[HID];
    bn_coeffs(stats, gamma, beta, sc, sh);
    __syncthreads();

    int gw = (blockIdx.x * blockDim.x + threadIdx.x) >> 5;
    if (gw >= N_NODES) return;
    int lane = threadIdx.x & 31;
    float2 scl = *reinterpret_cast<const float2*>(&sc[2 * lane]);
    float2 shf = *reinterpret_cast<const float2*>(&sh[2 * lane]);

    int deg = min(g_deg[gw], CAP);
    float epsv = 1.0f + *eps_p;

    float2 v = reinterpret_cast<const float2*>(h + (size_t)gw * HID)[lane];
    float2 a0 = {0, 0}, a1 = {0, 0};

    const int* bk = g_bucket + (size_t)gw * CAP;
    for (int base = 0; base < deg; base += 32) {
        int cnt = min(32, deg - base);                 // warp-uniform
        int s = (lane < cnt) ? bk[base + lane] : 0;
        for (int b = 0; b < cnt; b += 8) {             // warp-uniform trips
            int si[8];
#pragma unroll
            for (int i = 0; i < 8; i++)
                si[i] = __shfl_sync(0xffffffffu, s, b + i);
            float2 m[8];
#pragma unroll
            for (int i = 0; i < 8; i++)
                m[i] = reinterpret_cast<const float2*>(h + (size_t)si[i] * HID)[lane];
            int c8 = cnt - b;                          // warp-uniform
#pragma unroll
            for (int i = 0; i < 8; i++) {
                if (i < c8) {
                    if (i & 1) { a1.x += m[i].x; a1.y += m[i].y; }
                    else       { a0.x += m[i].x; a0.y += m[i].y; }
                }
            }
        }
    }
    float2 S;
    S.x = a0.x + a1.x;
    S.y = a0.y + a1.y;
    float cnt_sh = (float)deg + epsv;
    float2 o;
    o.x = fmaf(scl.x, fmaf(epsv, v.x, S.x), cnt_sh * shf.x);
    o.y = fmaf(scl.y, fmaf(epsv, v.y, S.y), cnt_sh * shf.y);
    reinterpret_cast<float2*>(out + (size_t)gw * HID)[lane] = o;
}

// ---------------- GEMM [N,K]@[K,64] + bias + ReLU (scalar tile) -------------
// 256 threads; tile ROWS x 64; thread: (ROWS/16) rows x 4 cols; k-vec by 4.
template <int K, int ROWS, int MINB, bool STATS>
__global__ __launch_bounds__(256, MINB)
void gemm_kernel(const float* __restrict__ X,
                 const float* __restrict__ W,
                 const float* __restrict__ bias,
                 float* __restrict__ out,
                 float* __restrict__ stats_out) {
    constexpr int RJ = ROWS / 16;
    __shared__ float sW[K * 64];
    __shared__ float sIn[ROWS * K];
    __shared__ float sSum[HID], sSq[HID];

    const int tid = threadIdx.x;
    const int tx  = tid & 15;
    const int ty  = tid >> 4;
    const size_t row0 = (size_t)blockIdx.x * ROWS;

    if (STATS && tid < HID) { sSum[tid] = 0.0f; sSq[tid] = 0.0f; }

    for (int i = tid; i < K * 64; i += 256) sW[i] = W[i];

    for (int i = tid; i < ROWS * K; i += 256) {
        size_t r = row0 + (size_t)(i / K);
        sIn[i] = (r < N_NODES) ? X[row0 * K + i] : 0.0f;
    }
    __syncthreads();

    float4 acc[RJ];
#pragma unroll
    for (int j = 0; j < RJ; j++) acc[j] = make_float4(0, 0, 0, 0);

#pragma unroll
    for (int k = 0; k < K; k += 4) {
        float4 w0 = *reinterpret_cast<const float4*>(&sW[(k + 0) * 64 + tx * 4]);
        float4 w1 = *reinterpret_cast<const float4*>(&sW[(k + 1) * 64 + tx * 4]);
        float4 w2 = *reinterpret_cast<const float4*>(&sW[(k + 2) * 64 + tx * 4]);
        float4 w3 = *reinterpret_cast<const float4*>(&sW[(k + 3) * 64 + tx * 4]);
#pragma unroll
        for (int j = 0; j < RJ; j++) {
            float4 a = *reinterpret_cast<const float4*>(&sIn[(ty * RJ + j) * K + k]);
            acc[j].x = fmaf(a.x, w0.x, acc[j].x);
            acc[j].y = fmaf(a.x, w0.y, acc[j].y);
            acc[j].z = fmaf(a.x, w0.z, acc[j].z);
            acc[j].w = fmaf(a.x, w0.w, acc[j].w);
            acc[j].x = fmaf(a.y, w1.x, acc[j].x);
            acc[j].y = fmaf(a.y, w1.y, acc[j].y);
            acc[j].z = fmaf(a.y, w1.z, acc[j].z);
            acc[j].w = fmaf(a.y, w1.w, acc[j].w);
            acc[j].x = fmaf(a.z, w2.x, acc[j].x);
            acc[j].y = fmaf(a.z, w2.y, acc[j].y);
            acc[j].z = fmaf(a.z, w2.z, acc[j].z);
            acc[j].w = fmaf(a.z, w2.w, acc[j].w);
            acc[j].x = fmaf(a.w, w3.x, acc[j].x);
            acc[j].y = fmaf(a.w, w3.y, acc[j].y);
            acc[j].z = fmaf(a.w, w3.z, acc[j].z);
            acc[j].w = fmaf(a.w, w3.w, acc[j].w);
        }
    }

    const float4 bv = reinterpret_cast<const float4*>(bias)[tx];
    float4 ls = make_float4(0, 0, 0, 0), lss = make_float4(0, 0, 0, 0);
#pragma unroll
    for (int j = 0; j < RJ; j++) {
        size_t row = row0 + ty * RJ + j;
        if (row >= N_NODES) break;
        float4 o;
        o.x = fmaxf(acc[j].x + bv.x, 0.0f);
        o.y = fmaxf(acc[j].y + bv.y, 0.0f);
        o.z = fmaxf(acc[j].z + bv.z, 0.0f);
        o.w = fmaxf(acc[j].w + bv.w, 0.0f);
        reinterpret_cast<float4*>(out + row * 64)[tx] = o;
        if (STATS) {
            ls.x += o.x; ls.y += o.y; ls.z += o.z; ls.w += o.w;
            lss.x += o.x * o.x; lss.y += o.y * o.y;
            lss.z += o.z * o.z; lss.w += o.w * o.w;
        }
    }

    if (STATS) {
        atomicAdd(&sSum[tx * 4 + 0], ls.x);
        atomicAdd(&sSum[tx * 4 + 1], ls.y);
        atomicAdd(&sSum[tx * 4 + 2], ls.z);
        atomicAdd(&sSum[tx * 4 + 3], ls.w);
        atomicAdd(&sSq[tx * 4 + 0], lss.x);
        atomicAdd(&sSq[tx * 4 + 1], lss.y);
        atomicAdd(&sSq[tx * 4 + 2], lss.z);
        atomicAdd(&sSq[tx * 4 + 3], lss.w);
        __syncthreads();
        if (tid < HID) {
            atomicAdd(&stats_out[tid],       sSum[tid]);
            atomicAdd(&stats_out[HID + tid], sSq[tid]);
        }
    }
}

// ---------------- fused BN3 + mean-pool + readout (batch is sorted) ---------
// Also re-zeroes g_deg for the next launch (graph replay invariant).
__global__ __launch_bounds__(128)
void pool_readout_kernel(const float* __restrict__ h,
                         const int* __restrict__ batch,
                         const float* __restrict__ stats,
                         const float* __restrict__ gamma,
                         const float* __restrict__ beta,
                         const float* __restrict__ Wf1,
                         const float* __restrict__ bf1,
                         const float* __restrict__ Wf2,
                         const float* __restrict__ bf2,
                         float* __restrict__ out) {
    __shared__ float sc[HID], sh[HID];
    __shared__ float part[4][HID];
    __shared__ float pooled[HID];
    __shared__ float hid[10];

    const int g   = blockIdx.x;
    const int tid = threadIdx.x;

    // reset g_deg for the next launch (1024 blocks x 128 threads = 131072 > N)
    {
        int z = g * 128 + tid;
        if (z < N_NODES) g_deg[z] = 0;
    }

    if (tid < HID) {
        const float invN = 1.0f / (float)N_NODES;
        float mean = stats[tid] * invN;
        float var  = stats[HID + tid] * invN - mean * mean;
        float s    = gamma[tid] * rsqrtf(var + 1e-5f);
        sc[tid] = s;
        sh[tid] = beta[tid] - mean * s;
    }

    int lo = 0, hi = N_NODES;
    while (lo < hi) { int m = (lo + hi) >> 1; if (batch[m] < g)     lo = m + 1; else hi = m; }
    const int start = lo;
    lo = start; hi = N_NODES;
    while (lo < hi) { int m = (lo + hi) >> 1; if (batch[m] < g + 1) lo = m + 1; else hi = m; }
    const int end = lo;

    const int cp = tid & 31;
    const int rg = tid >> 5;
    float2 a = make_float2(0, 0);
    for (int r = start + rg; r < end; r += 4) {
        float2 v = reinterpret_cast<const float2*>(h + (size_t)r * HID)[cp];
        a.x += v.x; a.y += v.y;
    }
    part[rg][cp * 2]     = a.x;
    part[rg][cp * 2 + 1] = a.y;
    __syncthreads();

    if (tid < 32) {
        float inv = 1.0f / fmaxf((float)(end - start), 1.0f);
        int c = tid * 2;
        float sx = part[0][c] + part[1][c] + part[2][c] + part[3][c];
        float sy = part[0][c + 1] + part[1][c + 1] + part[2][c + 1] + part[3][c + 1];
        pooled[c]     = (sx * inv) * sc[c]     + sh[c];
        pooled[c + 1] = (sy * inv) * sc[c + 1] + sh[c + 1];
    }
    __syncthreads();

    if (tid < 10) {
        float acc = bf1[tid];
        for (int k = 0; k < 64; k++) acc += pooled[k] * Wf1[k * 10 + tid];
        hid[tid] = fmaxf(acc, 0.0f);
    }
    __syncthreads();

    if (tid == 0) {
        float o = bf2[0];
#pragma unroll
        for (int j = 0; j < 10; j++) o += hid[j] * Wf2[j];
        out[g] = o;
    }
}

// ---------------- host launcher ----------------
static inline int cdiv(long long a, int b) { return (int)((a + b - 1) / b); }

extern "C" void kernel_launch(void* const* d_in, const int* in_sizes, int n_in,
                              void* d_out, int out_size) {
    (void)in_sizes; (void)n_in; (void)out_size;
    const float* x     = (const float*)d_in[0];
    const int*   ei    = (const int*)  d_in[1];
    const int*   batch = (const int*)  d_in[2];
    const float* W1a = (const float*)d_in[3];  const float* b1a = (const float*)d_in[4];
    const float* W1b = (const float*)d_in[5];  const float* b1b = (const float*)d_in[6];
    const float* e1  = (const float*)d_in[7];
    const float* g1  = (const float*)d_in[8];  const float* be1 = (const float*)d_in[9];
    const float* W2a = (const float*)d_in[10]; const float* b2a = (const float*)d_in[11];
    const float* W2b = (const float*)d_in[12]; const float* b2b = (const float*)d_in[13];
    const float* e2  = (const float*)d_in[14];
    const float* g2  = (const float*)d_in[15]; const float* be2 = (const float*)d_in[16];
    const float* W3a = (const float*)d_in[17]; const float* b3a = (const float*)d_in[18];
    const float* W3b = (const float*)d_in[19]; const float* b3b = (const float*)d_in[20];
    const float* e3  = (const float*)d_in[21];
    const float* g3  = (const float*)d_in[22]; const float* be3 = (const float*)d_in[23];
    const float* Wf1 = (const float*)d_in[24]; const float* bf1 = (const float*)d_in[25];
    const float* Wf2 = (const float*)d_in[26]; const float* bf2 = (const float*)d_in[27];
    float* out = (float*)d_out;

    const int* src = ei;
    const int* dst = ei + N_EDGES;

    void *p_c1, *p_h1, *p_h2, *p_stats;
    cudaGetSymbolAddress(&p_c1, g_c1);
    cudaGetSymbolAddress(&p_h1, g_h1);
    cudaGetSymbolAddress(&p_h2, g_h2);
    cudaGetSymbolAddress(&p_stats, g_stats);
    float* c1 = (float*)p_c1;
    float* h1 = (float*)p_h1;
    float* h2 = (float*)p_h2;
    float* st0 = (float*)p_stats;
    float* st1 = st0 + 2 * HID;
    float* st2 = st0 + 4 * HID;

    const int TB = 256;
    const int GB16 = cdiv(N_NODES, 64);    // 1563
    const int GB64 = cdiv(N_NODES, 128);   // 782

    bucket_kernel<<<cdiv(N_EDGES, TB), TB>>>(src, dst);

    // ===== layer 1 =====
    aggr16_kernel<<<cdiv(N_NODES * 4, TB), TB>>>(x, e1, c1);
    gemm_kernel<F_IN, 64, 4, false><<<GB16, TB>>>(c1, W1a, b1a, h1, nullptr);
    gemm_kernel<HID, 128, 3, true ><<<GB64, TB>>>(h1, W1b, b1b, h2, st0);

    // ===== layer 2 =====
    aggr64_kernel<<<cdiv(N_NODES * 32, TB), TB>>>(h2, st0, g1, be1, e2, h1);
    gemm_kernel<HID, 128, 3, false><<<GB64, TB>>>(h1, W2a, b2a, h2, nullptr);
    gemm_kernel<HID, 128, 3, true ><<<GB64, TB>>>(h2, W2b, b2b, h1, st1);

    // ===== layer 3 =====
    aggr64_kernel<<<cdiv(N_NODES * 32, TB), TB>>>(h1, st1, g2, be2, e3, h2);
    gemm_kernel<HID, 128, 3, false><<<GB64, TB>>>(h2, W3a, b3a, h1, nullptr);
    gemm_kernel<HID, 128, 3, true ><<<GB64, TB>>>(h1, W3b, b3b, h2, st2);

    // ===== fused BN3 + mean-pool + readout (also re-zeroes g_deg) =====
    pool_readout_kernel<<<G_GRAPHS, 128>>>(h2, batch, st2, g3, be3,
                                           Wf1, bf1, Wf2, bf2, out);
}

// round 16
// speedup vs baseline: 1.2523x; 1.0488x over previous
#include <cuda_runtime.h>
#include <cuda_bf16.h>
#include <cstddef>

#define N_NODES 100000
#define N_EDGES 1200000
#define HID 64
#define F_IN 16
#define G_GRAPHS 1024
#define CAP 96            // max in-degree capacity (Poisson(12): overflow ~1e-26)

// ---------------- scratch (device globals; no allocation) ----------------
// Invariants across launches: g_deg is zero at launch entry (zero-initialized
// at load; re-zeroed by pool_readout_kernel at the end of every launch).
// g_stats (ALL 384 floats) is zeroed at the start of every launch by
// bucket_kernel block 0.
__device__ float g_c1  [(size_t)N_NODES * F_IN];
__device__ float g_h1  [(size_t)N_NODES * HID];
__device__ float g_h2  [(size_t)N_NODES * HID];
__device__ int   g_deg [N_NODES];
__device__ int   g_bucket[(size_t)N_NODES * CAP];
__device__ float g_stats[3][2 * HID];

// BN scale/shift from accumulated sum/sumsq (training-mode batch stats)
__device__ __forceinline__ void bn_coeffs(const float* __restrict__ stats,
                                          const float* __restrict__ gamma,
                                          const float* __restrict__ beta,
                                          float* sc, float* sh) {
    int t = threadIdx.x;
    if (t < HID) {
        const float invN = 1.0f / (float)N_NODES;
        float mean = stats[t] * invN;
        float var  = stats[HID + t] * invN - mean * mean;
        float s    = gamma[t] * rsqrtf(var + 1e-5f);
        sc[t] = s;
        sh[t] = beta[t] - mean * s;
    }
}

// ---------------- bucket build (also zeroes ALL of g_stats for this launch) -
__global__ __launch_bounds__(256)
void bucket_kernel(const int* __restrict__ src, const int* __restrict__ dst) {
    int e = blockIdx.x * blockDim.x + threadIdx.x;
    if (blockIdx.x == 0) {
        int t = threadIdx.x;
        ((float*)g_stats)[t] = 0.0f;                       // [0,256)
        if (t < 3 * 2 * HID - 256) ((float*)g_stats)[256 + t] = 0.0f;  // [256,384)
    }
    if (e >= N_EDGES) return;
    int d = dst[e];
    int pos = atomicAdd(&g_deg[d], 1);
    if (pos < CAP) g_bucket[(size_t)d * CAP + pos] = src[e];
}

// ---------------- layer-1 gather-aggregate (16-wide, no BN) ----------------
__global__ __launch_bounds__(256)
void aggr16_kernel(const float* __restrict__ x,
                   const float* __restrict__ eps_p,
                   float* __restrict__ out) {
    int idx = blockIdx.x * blockDim.x + threadIdx.x;
    if (idx >= N_NODES * 4) return;
    int n = idx >> 2, q = idx & 3;
    int deg = min(g_deg[n], CAP);
    float epsv = 1.0f + *eps_p;
    float4 v = reinterpret_cast<const float4*>(x + (size_t)n * F_IN)[q];
    float4 a0 = make_float4(epsv * v.x, epsv * v.y, epsv * v.z, epsv * v.w);
    float4 a1 = make_float4(0, 0, 0, 0);
    const int* bk = g_bucket + (size_t)n * CAP;
    int i = 0;
    for (; i + 2 <= deg; i += 2) {
        int s0 = bk[i], s1 = bk[i + 1];
        float4 m0 = reinterpret_cast<const float4*>(x + (size_t)s0 * F_IN)[q];
        float4 m1 = reinterpret_cast<const float4*>(x + (size_t)s1 * F_IN)[q];
        a0.x += m0.x; a0.y += m0.y; a0.z += m0.z; a0.w += m0.w;
        a1.x += m1.x; a1.y += m1.y; a1.z += m1.z; a1.w += m1.w;
    }
    if (i < deg) {
        int s0 = bk[i];
        float4 m0 = reinterpret_cast<const float4*>(x + (size_t)s0 * F_IN)[q];
        a0.x += m0.x; a0.y += m0.y; a0.z += m0.z; a0.w += m0.w;
    }
    a0.x += a1.x; a0.y += a1.y; a0.z += a1.z; a0.w += a1.w;
    reinterpret_cast<float4*>(out + (size_t)n * F_IN)[q] = a0;
}

// ---------------- 64-wide gather-aggregate, BN after sum, 8 loads in flight -
// out[n] = sc * ((1+eps)*h_n + sum_j h_j) + (deg + 1 + eps) * sh
__global__ __launch_bounds__(256)
void aggr64_kernel(const float* __restrict__ h,
                   const float* __restrict__ stats,
                   const float* __restrict__ gamma,
                   const float* __restrict__ beta,
                   const float* __restrict__ eps_p,
                   float* __restrict__ out) {
    __shared__ float sc[HID], sh[HID];
    bn_coeffs(stats, gamma, beta, sc, sh);
    __syncthreads();

    int gw = (blockIdx.x * blockDim.x + threadIdx.x) >> 5;
    if (gw >= N_NODES) return;
    int lane = threadIdx.x & 31;
    float2 scl = *reinterpret_cast<const float2*>(&sc[2 * lane]);
    float2 shf = *reinterpret_cast<const float2*>(&sh[2 * lane]);

    int deg = min(g_deg[gw], CAP);
    float epsv = 1.0f + *eps_p;

    float2 v = reinterpret_cast<const float2*>(h + (size_t)gw * HID)[lane];
    float2 a0 = {0, 0}, a1 = {0, 0};

    const int* bk = g_bucket + (size_t)gw * CAP;
    for (int base = 0; base < deg; base += 32) {
        int cnt = min(32, deg - base);                 // warp-uniform
        int s = (lane < cnt) ? bk[base + lane] : 0;
        for (int b = 0; b < cnt; b += 8) {             // warp-uniform trips
            int si[8];
#pragma unroll
            for (int i = 0; i < 8; i++)
                si[i] = __shfl_sync(0xffffffffu, s, b + i);
            float2 m[8];
#pragma unroll
            for (int i = 0; i < 8; i++)
                m[i] = reinterpret_cast<const float2*>(h + (size_t)si[i] * HID)[lane];
            int c8 = cnt - b;                          // warp-uniform
#pragma unroll
            for (int i = 0; i < 8; i++) {
                if (i < c8) {
                    if (i & 1) { a1.x += m[i].x; a1.y += m[i].y; }
                    else       { a0.x += m[i].x; a0.y += m[i].y; }
                }
            }
        }
    }
    float2 S;
    S.x = a0.x + a1.x;
    S.y = a0.y + a1.y;
    float cnt_sh = (float)deg + epsv;
    float2 o;
    o.x = fmaf(scl.x, fmaf(epsv, v.x, S.x), cnt_sh * shf.x);
    o.y = fmaf(scl.y, fmaf(epsv, v.y, S.y), cnt_sh * shf.y);
    reinterpret_cast<float2*>(out + (size_t)gw * HID)[lane] = o;
}

// ---------------- GEMM [N,K]@[K,64] + bias + ReLU (scalar tile) -------------
// 256 threads; tile ROWS x 64; thread: (ROWS/16) rows x 4 cols; k-vec by 4.
// STATS: atomic-free per-warp partials (shfl fold + plain STS), then one
// global atomicAdd per column per block.
template <int K, int ROWS, int MINB, bool STATS>
__global__ __launch_bounds__(256, MINB)
void gemm_kernel(const float* __restrict__ X,
                 const float* __restrict__ W,
                 const float* __restrict__ bias,
                 float* __restrict__ out,
                 float* __restrict__ stats_out) {
    constexpr int RJ = ROWS / 16;
    __shared__ float sW[K * 64];
    __shared__ float sIn[ROWS * K];
    __shared__ float sPartSum[8][HID];
    __shared__ float sPartSq [8][HID];

    const int tid = threadIdx.x;
    const int tx  = tid & 15;
    const int ty  = tid >> 4;
    const size_t row0 = (size_t)blockIdx.x * ROWS;

    for (int i = tid; i < K * 64; i += 256) sW[i] = W[i];

    for (int i = tid; i < ROWS * K; i += 256) {
        size_t r = row0 + (size_t)(i / K);
        sIn[i] = (r < N_NODES) ? X[row0 * K + i] : 0.0f;
    }
    __syncthreads();

    float4 acc[RJ];
#pragma unroll
    for (int j = 0; j < RJ; j++) acc[j] = make_float4(0, 0, 0, 0);

#pragma unroll
    for (int k = 0; k < K; k += 4) {
        float4 w0 = *reinterpret_cast<const float4*>(&sW[(k + 0) * 64 + tx * 4]);
        float4 w1 = *reinterpret_cast<const float4*>(&sW[(k + 1) * 64 + tx * 4]);
        float4 w2 = *reinterpret_cast<const float4*>(&sW[(k + 2) * 64 + tx * 4]);
        float4 w3 = *reinterpret_cast<const float4*>(&sW[(k + 3) * 64 + tx * 4]);
#pragma unroll
        for (int j = 0; j < RJ; j++) {
            float4 a = *reinterpret_cast<const float4*>(&sIn[(ty * RJ + j) * K + k]);
            acc[j].x = fmaf(a.x, w0.x, acc[j].x);
            acc[j].y = fmaf(a.x, w0.y, acc[j].y);
            acc[j].z = fmaf(a.x, w0.z, acc[j].z);
            acc[j].w = fmaf(a.x, w0.w, acc[j].w);
            acc[j].x = fmaf(a.y, w1.x, acc[j].x);
            acc[j].y = fmaf(a.y, w1.y, acc[j].y);
            acc[j].z = fmaf(a.y, w1.z, acc[j].z);
            acc[j].w = fmaf(a.y, w1.w, acc[j].w);
            acc[j].x = fmaf(a.z, w2.x, acc[j].x);
            acc[j].y = fmaf(a.z, w2.y, acc[j].y);
            acc[j].z = fmaf(a.z, w2.z, acc[j].z);
            acc[j].w = fmaf(a.z, w2.w, acc[j].w);
            acc[j].x = fmaf(a.w, w3.x, acc[j].x);
            acc[j].y = fmaf(a.w, w3.y, acc[j].y);
            acc[j].z = fmaf(a.w, w3.z, acc[j].z);
            acc[j].w = fmaf(a.w, w3.w, acc[j].w);
        }
    }

    const float4 bv = reinterpret_cast<const float4*>(bias)[tx];
    float4 ls = make_float4(0, 0, 0, 0), lss = make_float4(0, 0, 0, 0);
#pragma unroll
    for (int j = 0; j < RJ; j++) {
        size_t row = row0 + ty * RJ + j;
        if (row >= N_NODES) break;
        float4 o;
        o.x = fmaxf(acc[j].x + bv.x, 0.0f);
        o.y = fmaxf(acc[j].y + bv.y, 0.0f);
        o.z = fmaxf(acc[j].z + bv.z, 0.0f);
        o.w = fmaxf(acc[j].w + bv.w, 0.0f);
        reinterpret_cast<float4*>(out + row * 64)[tx] = o;
        if (STATS) {
            ls.x += o.x; ls.y += o.y; ls.z += o.z; ls.w += o.w;
            lss.x += o.x * o.x; lss.y += o.y * o.y;
            lss.z += o.z * o.z; lss.w += o.w * o.w;
        }
    }

    if (STATS) {
        // lanes l and l^16 share tx -> fold, lanes 0..15 hold warp partials
        const int w    = tid >> 5;
        const int lane = tid & 31;
        ls.x  += __shfl_xor_sync(0xffffffffu, ls.x,  16);
        ls.y  += __shfl_xor_sync(0xffffffffu, ls.y,  16);
        ls.z  += __shfl_xor_sync(0xffffffffu, ls.z,  16);
        ls.w  += __shfl_xor_sync(0xffffffffu, ls.w,  16);
        lss.x += __shfl_xor_sync(0xffffffffu, lss.x, 16);
        lss.y += __shfl_xor_sync(0xffffffffu, lss.y, 16);
        lss.z += __shfl_xor_sync(0xffffffffu, lss.z, 16);
        lss.w += __shfl_xor_sync(0xffffffffu, lss.w, 16);
        if (lane < 16) {
            *reinterpret_cast<float4*>(&sPartSum[w][tx * 4]) = ls;
            *reinterpret_cast<float4*>(&sPartSq [w][tx * 4]) = lss;
        }
        __syncthreads();
        if (tid < HID) {
            float s = 0.0f, q = 0.0f;
#pragma unroll
            for (int ww = 0; ww < 8; ww++) {
                s += sPartSum[ww][tid];
                q += sPartSq [ww][tid];
            }
            atomicAdd(&stats_out[tid],       s);
            atomicAdd(&stats_out[HID + tid], q);
        }
    }
}

// ---------------- fused BN3 + mean-pool + readout (batch is sorted) ---------
// Also re-zeroes g_deg for the next launch (graph replay invariant).
__global__ __launch_bounds__(128)
void pool_readout_kernel(const float* __restrict__ h,
                         const int* __restrict__ batch,
                         const float* __restrict__ stats,
                         const float* __restrict__ gamma,
                         const float* __restrict__ beta,
                         const float* __restrict__ Wf1,
                         const float* __restrict__ bf1,
                         const float* __restrict__ Wf2,
                         const float* __restrict__ bf2,
                         float* __restrict__ out) {
    __shared__ float sc[HID], sh[HID];
    __shared__ float part[4][HID];
    __shared__ float pooled[HID];
    __shared__ float hid[10];

    const int g   = blockIdx.x;
    const int tid = threadIdx.x;

    // reset g_deg for the next launch (1024 blocks x 128 threads = 131072 > N)
    {
        int z = g * 128 + tid;
        if (z < N_NODES) g_deg[z] = 0;
    }

    if (tid < HID) {
        const float invN = 1.0f / (float)N_NODES;
        float mean = stats[tid] * invN;
        float var  = stats[HID + tid] * invN - mean * mean;
        float s    = gamma[tid] * rsqrtf(var + 1e-5f);
        sc[tid] = s;
        sh[tid] = beta[tid] - mean * s;
    }

    int lo = 0, hi = N_NODES;
    while (lo < hi) { int m = (lo + hi) >> 1; if (batch[m] < g)     lo = m + 1; else hi = m; }
    const int start = lo;
    lo = start; hi = N_NODES;
    while (lo < hi) { int m = (lo + hi) >> 1; if (batch[m] < g + 1) lo = m + 1; else hi = m; }
    const int end = lo;

    const int cp = tid & 31;
    const int rg = tid >> 5;
    float2 a = make_float2(0, 0);
    for (int r = start + rg; r < end; r += 4) {
        float2 v = reinterpret_cast<const float2*>(h + (size_t)r * HID)[cp];
        a.x += v.x; a.y += v.y;
    }
    part[rg][cp * 2]     = a.x;
    part[rg][cp * 2 + 1] = a.y;
    __syncthreads();

    if (tid < 32) {
        float inv = 1.0f / fmaxf((float)(end - start), 1.0f);
        int c = tid * 2;
        float sx = part[0][c] + part[1][c] + part[2][c] + part[3][c];
        float sy = part[0][c + 1] + part[1][c + 1] + part[2][c + 1] + part[3][c + 1];
        pooled[c]     = (sx * inv) * sc[c]     + sh[c];
        pooled[c + 1] = (sy * inv) * sc[c + 1] + sh[c + 1];
    }
    __syncthreads();

    if (tid < 10) {
        float acc = bf1[tid];
        for (int k = 0; k < 64; k++) acc += pooled[k] * Wf1[k * 10 + tid];
        hid[tid] = fmaxf(acc, 0.0f);
    }
    __syncthreads();

    if (tid == 0) {
        float o = bf2[0];
#pragma unroll
        for (int j = 0; j < 10; j++) o += hid[j] * Wf2[j];
        out[g] = o;
    }
}

// ---------------- host launcher ----------------
static inline int cdiv(long long a, int b) { return (int)((a + b - 1) / b); }

extern "C" void kernel_launch(void* const* d_in, const int* in_sizes, int n_in,
                              void* d_out, int out_size) {
    (void)in_sizes; (void)n_in; (void)out_size;
    const float* x     = (const float*)d_in[0];
    const int*   ei    = (const int*)  d_in[1];
    const int*   batch = (const int*)  d_in[2];
    const float* W1a = (const float*)d_in[3];  const float* b1a = (const float*)d_in[4];
    const float* W1b = (const float*)d_in[5];  const float* b1b = (const float*)d_in[6];
    const float* e1  = (const float*)d_in[7];
    const float* g1  = (const float*)d_in[8];  const float* be1 = (const float*)d_in[9];
    const float* W2a = (const float*)d_in[10]; const float* b2a = (const float*)d_in[11];
    const float* W2b = (const float*)d_in[12]; const float* b2b = (const float*)d_in[13];
    const float* e2  = (const float*)d_in[14];
    const float* g2  = (const float*)d_in[15]; const float* be2 = (const float*)d_in[16];
    const float* W3a = (const float*)d_in[17]; const float* b3a = (const float*)d_in[18];
    const float* W3b = (const float*)d_in[19]; const float* b3b = (const float*)d_in[20];
    const float* e3  = (const float*)d_in[21];
    const float* g3  = (const float*)d_in[22]; const float* be3 = (const float*)d_in[23];
    const float* Wf1 = (const float*)d_in[24]; const float* bf1 = (const float*)d_in[25];
    const float* Wf2 = (const float*)d_in[26]; const float* bf2 = (const float*)d_in[27];
    float* out = (float*)d_out;

    const int* src = ei;
    const int* dst = ei + N_EDGES;

    void *p_c1, *p_h1, *p_h2, *p_stats;
    cudaGetSymbolAddress(&p_c1, g_c1);
    cudaGetSymbolAddress(&p_h1, g_h1);
    cudaGetSymbolAddress(&p_h2, g_h2);
    cudaGetSymbolAddress(&p_stats, g_stats);
    float* c1 = (float*)p_c1;
    float* h1 = (float*)p_h1;
    float* h2 = (float*)p_h2;
    float* st0 = (float*)p_stats;
    float* st1 = st0 + 2 * HID;
    float* st2 = st0 + 4 * HID;

    const int TB = 256;
    const int GB16 = cdiv(N_NODES, 64);    // 1563
    const int GB64 = cdiv(N_NODES, 128);   // 782

    bucket_kernel<<<cdiv(N_EDGES, TB), TB>>>(src, dst);

    // ===== layer 1 =====
    aggr16_kernel<<<cdiv(N_NODES * 4, TB), TB>>>(x, e1, c1);
    gemm_kernel<F_IN, 64, 4, false><<<GB16, TB>>>(c1, W1a, b1a, h1, nullptr);
    gemm_kernel<HID, 128, 3, true ><<<GB64, TB>>>(h1, W1b, b1b, h2, st0);

    // ===== layer 2 =====
    aggr64_kernel<<<cdiv(N_NODES * 32, TB), TB>>>(h2, st0, g1, be1, e2, h1);
    gemm_kernel<HID, 128, 3, false><<<GB64, TB>>>(h1, W2a, b2a, h2, nullptr);
    gemm_kernel<HID, 128, 3, true ><<<GB64, TB>>>(h2, W2b, b2b, h1, st1);

    // ===== layer 3 =====
    aggr64_kernel<<<cdiv(N_NODES * 32, TB), TB>>>(h1, st1, g2, be2, e3, h2);
    gemm_kernel<HID, 128, 3, false><<<GB64, TB>>>(h2, W3a, b3a, h1, nullptr);
    gemm_kernel<HID, 128, 3, true ><<<GB64, TB>>>(h1, W3b, b3b, h2, st2);

    // ===== fused BN3 + mean-pool + readout (also re-zeroes g_deg) =====
    pool_readout_kernel<<<G_GRAPHS, 128>>>(h2, batch, st2, g3, be3,
                                           Wf1, bf1, Wf2, bf2, out);
}